// round 9
// baseline (speedup 1.0000x reference)
#include <cuda_runtime.h>
#include <cuda_bf16.h>
#include <mma.h>
#include <cstdint>
#include <cstddef>

using namespace nvcuda;

// Problem constants
#define BB 2
#define LL 1024
#define HH 2048
#define HD 64
#define NQ 32
#define NK 4
#define NPREV 28

// Scratch (device globals)
__device__ float g_Q[(size_t)BB * NQ * LL * HD];
__device__ float g_K[(size_t)BB * NQ * LL * HD];
__device__ float g_V[(size_t)BB * NQ * LL * HD];
__device__ float g_AO[(size_t)BB * LL * (NQ * HD)];

// ---------------------------------------------------------------------------
// TF32 tensor-core GEMM: C[m,n] = sum_k A[m,k] * W[n,k]
// A: [M,K] rm, W: [N,K] rm. BM=BN=128, BK=32, 256 threads, wmma m16n16k8.
// scatter=1: n=(h,d) m=(b,l) -> C[((b*32+head_off+h)*1024+l)*64+d]
// ---------------------------------------------------------------------------
#define GLD 36   // smem leading dim (floats): 144B, 16B-aligned rows, pad-4

__global__ void __launch_bounds__(256) gemm_tf32(
    const float* __restrict__ A, const float* __restrict__ W,
    float* __restrict__ C, int M, int N, int K, int scatter, int head_off)
{
    __shared__ float As[128][GLD];
    __shared__ float Bs[128][GLD];

    const int t    = threadIdx.x;
    const int warp = t >> 5;
    const int wm   = warp & 3;   // 4 warps along M (32 rows each)
    const int wn   = warp >> 2;  // 2 warps along N (64 cols each)
    const int row0 = blockIdx.y * 128;
    const int col0 = blockIdx.x * 128;

    wmma::fragment<wmma::accumulator, 16, 16, 8, float> acc[2][4];
#pragma unroll
    for (int i = 0; i < 2; i++)
#pragma unroll
        for (int j = 0; j < 4; j++) wmma::fill_fragment(acc[i][j], 0.0f);

    for (int bk = 0; bk < K; bk += 32) {
        // Fill smem (convert to tf32 once here; fragments load raw after)
#pragma unroll
        for (int q = 0; q < 4; q++) {
            int f  = q * 256 + t;          // 0..1023
            int r  = f >> 3;
            int c4 = f & 7;
            float4 va = *(const float4*)(A + (size_t)(row0 + r) * K + bk + c4 * 4);
            float* da = &As[r][c4 * 4];
            da[0] = wmma::__float_to_tf32(va.x);
            da[1] = wmma::__float_to_tf32(va.y);
            da[2] = wmma::__float_to_tf32(va.z);
            da[3] = wmma::__float_to_tf32(va.w);
            float4 vb = *(const float4*)(W + (size_t)(col0 + r) * K + bk + c4 * 4);
            float* db = &Bs[r][c4 * 4];
            db[0] = wmma::__float_to_tf32(vb.x);
            db[1] = wmma::__float_to_tf32(vb.y);
            db[2] = wmma::__float_to_tf32(vb.z);
            db[3] = wmma::__float_to_tf32(vb.w);
        }
        __syncthreads();

#pragma unroll
        for (int ks = 0; ks < 4; ks++) {
            wmma::fragment<wmma::matrix_a, 16, 16, 8, wmma::precision::tf32,
                           wmma::row_major> af[2];
#pragma unroll
            for (int i = 0; i < 2; i++)
                wmma::load_matrix_sync(af[i], &As[wm * 32 + i * 16][ks * 8], GLD);
#pragma unroll
            for (int j = 0; j < 4; j++) {
                wmma::fragment<wmma::matrix_b, 16, 16, 8, wmma::precision::tf32,
                               wmma::col_major> bf;
                wmma::load_matrix_sync(bf, &Bs[wn * 64 + j * 16][ks * 8], GLD);
#pragma unroll
                for (int i = 0; i < 2; i++)
                    wmma::mma_sync(acc[i][j], af[i], bf, acc[i][j]);
            }
        }
        __syncthreads();
    }

    // Epilogue: each 16x16 tile stores directly (never straddles head/batch)
#pragma unroll
    for (int i = 0; i < 2; i++) {
        int m0 = row0 + wm * 32 + i * 16;
#pragma unroll
        for (int j = 0; j < 4; j++) {
            int n0 = col0 + wn * 64 + j * 16;
            if (scatter) {
                int b = m0 >> 10, l = m0 & 1023;
                int h = n0 >> 6,  d = n0 & 63;
                float* dst = C + ((size_t)((b * 32 + head_off + h) * 1024 + l)) * 64 + d;
                wmma::store_matrix_sync(dst, acc[i][j], 64, wmma::mem_row_major);
            } else {
                wmma::store_matrix_sync(C + (size_t)m0 * N + n0, acc[i][j], N,
                                        wmma::mem_row_major);
            }
        }
    }
}

// ---------------------------------------------------------------------------
// RoPE + cache gather (unchanged)
// ---------------------------------------------------------------------------
__global__ void __launch_bounds__(256) rope_gather_kernel(
    const float* __restrict__ prev_k, const float* __restrict__ prev_v,
    const float* __restrict__ cosp,   const float* __restrict__ sinp)
{
    unsigned t = blockIdx.x * 256u + threadIdx.x;
    int d = t & 31;
    int l = (t >> 5) & 1023;
    int h = (t >> 15) & 31;
    int b = t >> 20;

    float c = cosp[l * 64 + d];
    float s = sinp[l * 64 + d];

    size_t base = ((size_t)(b * 32 + h) * 1024 + l) * 64;

    {
        float* q = g_Q + base;
        float x1 = q[d], x2 = q[d + 32];
        q[d]      = x1 * c - x2 * s;
        q[d + 32] = x2 * c + x1 * s;
    }
    {
        float* k = g_K + base;
        float y1, y2;
        if (h < NPREV) {
            const float* pk = prev_k + ((size_t)(b * NPREV + h) * 1024 + l) * 64;
            y1 = pk[d]; y2 = pk[d + 32];
        } else {
            y1 = k[d]; y2 = k[d + 32];
        }
        k[d]      = y1 * c - y2 * s;
        k[d + 32] = y2 * c + y1 * s;
    }
    if (h < NPREV) {
        const float* pv = prev_v + ((size_t)(b * NPREV + h) * 1024 + l) * 64;
        float* v = g_V + base;
        v[d]      = pv[d];
        v[d + 32] = pv[d + 32];
    }
}

// ---------------------------------------------------------------------------
// Flash attention (fp32, causal) — unchanged from R7 passing version
// ---------------------------------------------------------------------------
#define FA_LD 68
#define FA_SMEM (3 * 64 * FA_LD * 4)

__global__ void __launch_bounds__(256) flash_kernel(
    const float* __restrict__ Q, const float* __restrict__ K,
    const float* __restrict__ V, float* __restrict__ AO)
{
    extern __shared__ float sm[];
    float* Qs = sm;
    float* Ks = sm + 64 * FA_LD;
    float* Vs = sm + 2 * 64 * FA_LD;

    const int t  = threadIdx.x;
    const int tx = t & 15;
    const int ty = t >> 4;
    const int qt = blockIdx.x;
    const int h  = blockIdx.y;
    const int b  = blockIdx.z;
    const int q0 = qt * 64;

    const size_t bh_off = (size_t)(b * 32 + h) * 1024 * 64;
    const float* Qp = Q + bh_off;
    const float* Kp = K + bh_off;
    const float* Vp = V + bh_off;

#pragma unroll
    for (int q = 0; q < 4; q++) {
        int f  = q * 256 + t;
        int r  = f >> 4;
        int c4 = f & 15;
        float4 v = *(const float4*)(Qp + (size_t)(q0 + r) * 64 + c4 * 4);
        float* dst = Qs + r * FA_LD + c4 * 4;
        dst[0] = v.x; dst[1] = v.y; dst[2] = v.z; dst[3] = v.w;
    }

    float m_i[4], l_i[4], o_[4][4];
#pragma unroll
    for (int i = 0; i < 4; i++) {
        m_i[i] = -1e30f; l_i[i] = 0.0f;
#pragma unroll
        for (int j = 0; j < 4; j++) o_[i][j] = 0.0f;
    }

    for (int j = 0; j <= qt; j++) {
        __syncthreads();
#pragma unroll
        for (int q = 0; q < 4; q++) {
            int f  = q * 256 + t;
            int r  = f >> 4;
            int c4 = f & 15;
            size_t goff = (size_t)(j * 64 + r) * 64 + c4 * 4;
            float4 kv = *(const float4*)(Kp + goff);
            float* dk = Ks + r * FA_LD + c4 * 4;
            dk[0] = kv.x; dk[1] = kv.y; dk[2] = kv.z; dk[3] = kv.w;
            float4 vv = *(const float4*)(Vp + goff);
            float* dv = Vs + r * FA_LD + c4 * 4;
            dv[0] = vv.x; dv[1] = vv.y; dv[2] = vv.z; dv[3] = vv.w;
        }
        __syncthreads();

        float s_[4][4];
#pragma unroll
        for (int i = 0; i < 4; i++)
#pragma unroll
            for (int jj = 0; jj < 4; jj++) s_[i][jj] = 0.0f;

#pragma unroll
        for (int d4 = 0; d4 < 16; d4++) {
            float4 a[4], kk[4];
#pragma unroll
            for (int i = 0; i < 4; i++)
                a[i] = *(const float4*)(Qs + (ty * 4 + i) * FA_LD + d4 * 4);
#pragma unroll
            for (int jj = 0; jj < 4; jj++)
                kk[jj] = *(const float4*)(Ks + (jj * 16 + tx) * FA_LD + d4 * 4);
#pragma unroll
            for (int i = 0; i < 4; i++)
#pragma unroll
                for (int jj = 0; jj < 4; jj++) {
                    s_[i][jj] = fmaf(a[i].x, kk[jj].x, s_[i][jj]);
                    s_[i][jj] = fmaf(a[i].y, kk[jj].y, s_[i][jj]);
                    s_[i][jj] = fmaf(a[i].z, kk[jj].z, s_[i][jj]);
                    s_[i][jj] = fmaf(a[i].w, kk[jj].w, s_[i][jj]);
                }
        }

        const float scale = 0.125f;
#pragma unroll
        for (int i = 0; i < 4; i++)
#pragma unroll
            for (int jj = 0; jj < 4; jj++) s_[i][jj] *= scale;

        if (j == qt) {
#pragma unroll
            for (int i = 0; i < 4; i++)
#pragma unroll
                for (int jj = 0; jj < 4; jj++)
                    if ((jj * 16 + tx) > (ty * 4 + i)) s_[i][jj] = -1e30f;
        }

#pragma unroll
        for (int i = 0; i < 4; i++) {
            float mx = fmaxf(fmaxf(s_[i][0], s_[i][1]), fmaxf(s_[i][2], s_[i][3]));
#pragma unroll
            for (int off = 1; off < 16; off <<= 1)
                mx = fmaxf(mx, __shfl_xor_sync(0xffffffffu, mx, off));
            float mnew = fmaxf(m_i[i], mx);
            float corr = __expf(m_i[i] - mnew);
            float rs = 0.0f;
#pragma unroll
            for (int jj = 0; jj < 4; jj++) {
                s_[i][jj] = __expf(s_[i][jj] - mnew);
                rs += s_[i][jj];
            }
#pragma unroll
            for (int off = 1; off < 16; off <<= 1)
                rs += __shfl_xor_sync(0xffffffffu, rs, off);
            l_i[i] = l_i[i] * corr + rs;
            m_i[i] = mnew;
#pragma unroll
            for (int jj = 0; jj < 4; jj++) o_[i][jj] *= corr;
        }

        __syncthreads();
#pragma unroll
        for (int i = 0; i < 4; i++)
#pragma unroll
            for (int jj = 0; jj < 4; jj++)
                Ks[(ty * 4 + i) * FA_LD + jj * 16 + tx] = s_[i][jj];
        __syncthreads();

#pragma unroll
        for (int c4 = 0; c4 < 16; c4++) {
            float4 p4[4];
#pragma unroll
            for (int i = 0; i < 4; i++)
                p4[i] = *(const float4*)(Ks + (ty * 4 + i) * FA_LD + c4 * 4);
#pragma unroll
            for (int cc = 0; cc < 4; cc++) {
                float vv[4];
#pragma unroll
                for (int jj = 0; jj < 4; jj++)
                    vv[jj] = Vs[(c4 * 4 + cc) * FA_LD + jj * 16 + tx];
#pragma unroll
                for (int i = 0; i < 4; i++) {
                    float pval = (cc == 0) ? p4[i].x : (cc == 1) ? p4[i].y
                               : (cc == 2) ? p4[i].z : p4[i].w;
#pragma unroll
                    for (int jj = 0; jj < 4; jj++)
                        o_[i][jj] = fmaf(pval, vv[jj], o_[i][jj]);
                }
            }
        }
    }

#pragma unroll
    for (int i = 0; i < 4; i++) {
        float rl = 1.0f / l_i[i];
        size_t row = (size_t)b * 1024 + (q0 + ty * 4 + i);
#pragma unroll
        for (int jj = 0; jj < 4; jj++)
            AO[row * 2048 + h * 64 + jj * 16 + tx] = o_[i][jj] * rl;
    }
}

// ---------------------------------------------------------------------------
// Launch
// ---------------------------------------------------------------------------
extern "C" void kernel_launch(void* const* d_in, const int* in_sizes, int n_in,
                              void* d_out, int out_size)
{
    const float* hs   = (const float*)d_in[0];
    const float* pk   = (const float*)d_in[1];
    const float* pv   = (const float*)d_in[2];
    const float* Wq   = (const float*)d_in[3];
    const float* Wk   = (const float*)d_in[4];
    const float* Wv   = (const float*)d_in[5];
    const float* Wo   = (const float*)d_in[6];
    const float* cosp = (const float*)d_in[7];
    const float* sinp = (const float*)d_in[8];
    float* out = (float*)d_out;

    float *Qb, *Kb, *Vb, *AO;
    cudaGetSymbolAddress((void**)&Qb, g_Q);
    cudaGetSymbolAddress((void**)&Kb, g_K);
    cudaGetSymbolAddress((void**)&Vb, g_V);
    cudaGetSymbolAddress((void**)&AO, g_AO);

    cudaFuncSetAttribute(flash_kernel,
                         cudaFuncAttributeMaxDynamicSharedMemorySize, FA_SMEM);

    // QKV projections on tensor pipe (tf32)
    gemm_tf32<<<dim3(16, 16), 256>>>(hs, Wq, Qb, 2048, 2048, 2048, 1, 0);
    gemm_tf32<<<dim3(2, 16),  256>>>(hs, Wk, Kb, 2048, 256,  2048, 1, NPREV);
    gemm_tf32<<<dim3(2, 16),  256>>>(hs, Wv, Vb, 2048, 256,  2048, 1, NPREV);

    // Cache gather + RoPE
    rope_gather_kernel<<<8192, 256>>>(pk, pv, cosp, sinp);

    // Causal flash attention -> g_AO [B, L, 2048]
    flash_kernel<<<dim3(16, 32, 2), 256, FA_SMEM>>>(Qb, Kb, Vb, AO);

    // Output projection (tf32)
    gemm_tf32<<<dim3(16, 16), 256>>>(AO, Wo, out, 2048, 2048, 2048, 0, 0);
}

// round 10
// speedup vs baseline: 1.0058x; 1.0058x over previous
#include <cuda_runtime.h>
#include <cuda_bf16.h>
#include <mma.h>
#include <cstdint>
#include <cstddef>

using namespace nvcuda;

// Problem constants
#define BB 2
#define LL 1024
#define HH 2048
#define HD 64
#define NQ 32
#define NK 4
#define NPREV 28

// Scratch (device globals)
__device__ float g_Q[(size_t)BB * NQ * LL * HD];
__device__ float g_K[(size_t)BB * NQ * LL * HD];
__device__ float g_V[(size_t)BB * NQ * LL * HD];
__device__ float g_AO[(size_t)BB * LL * (NQ * HD)];

// ---------------------------------------------------------------------------
// TF32 tensor-core GEMM: C[m,n] = sum_k A[m,k] * W[n,k]
// A: [M,K] rm, W: [N,K] rm. BM=BN=128, BK=32, 256 threads, wmma m16n16k8.
// scatter=1: n=(h,d) m=(b,l) -> C[((b*32+head_off+h)*1024+l)*64+d]
// ---------------------------------------------------------------------------
#define GLD 36   // smem leading dim (floats): 144B, 16B-aligned rows, pad-4

__global__ void __launch_bounds__(256) gemm_tf32(
    const float* __restrict__ A, const float* __restrict__ W,
    float* __restrict__ C, int M, int N, int K, int scatter, int head_off)
{
    __shared__ float As[128][GLD];
    __shared__ float Bs[128][GLD];

    const int t    = threadIdx.x;
    const int warp = t >> 5;
    const int wm   = warp & 3;   // 4 warps along M (32 rows each)
    const int wn   = warp >> 2;  // 2 warps along N (64 cols each)
    const int row0 = blockIdx.y * 128;
    const int col0 = blockIdx.x * 128;

    wmma::fragment<wmma::accumulator, 16, 16, 8, float> acc[2][4];
#pragma unroll
    for (int i = 0; i < 2; i++)
#pragma unroll
        for (int j = 0; j < 4; j++) wmma::fill_fragment(acc[i][j], 0.0f);

    for (int bk = 0; bk < K; bk += 32) {
        // Fill smem (convert to tf32 once here; fragments load raw after)
#pragma unroll
        for (int q = 0; q < 4; q++) {
            int f  = q * 256 + t;          // 0..1023
            int r  = f >> 3;
            int c4 = f & 7;
            float4 va = *(const float4*)(A + (size_t)(row0 + r) * K + bk + c4 * 4);
            float* da = &As[r][c4 * 4];
            da[0] = wmma::__float_to_tf32(va.x);
            da[1] = wmma::__float_to_tf32(va.y);
            da[2] = wmma::__float_to_tf32(va.z);
            da[3] = wmma::__float_to_tf32(va.w);
            float4 vb = *(const float4*)(W + (size_t)(col0 + r) * K + bk + c4 * 4);
            float* db = &Bs[r][c4 * 4];
            db[0] = wmma::__float_to_tf32(vb.x);
            db[1] = wmma::__float_to_tf32(vb.y);
            db[2] = wmma::__float_to_tf32(vb.z);
            db[3] = wmma::__float_to_tf32(vb.w);
        }
        __syncthreads();

#pragma unroll
        for (int ks = 0; ks < 4; ks++) {
            wmma::fragment<wmma::matrix_a, 16, 16, 8, wmma::precision::tf32,
                           wmma::row_major> af[2];
#pragma unroll
            for (int i = 0; i < 2; i++)
                wmma::load_matrix_sync(af[i], &As[wm * 32 + i * 16][ks * 8], GLD);
#pragma unroll
            for (int j = 0; j < 4; j++) {
                wmma::fragment<wmma::matrix_b, 16, 16, 8, wmma::precision::tf32,
                               wmma::col_major> bf;
                wmma::load_matrix_sync(bf, &Bs[wn * 64 + j * 16][ks * 8], GLD);
#pragma unroll
                for (int i = 0; i < 2; i++)
                    wmma::mma_sync(acc[i][j], af[i], bf, acc[i][j]);
            }
        }
        __syncthreads();
    }

    // Epilogue: each 16x16 tile stores directly (never straddles head/batch)
#pragma unroll
    for (int i = 0; i < 2; i++) {
        int m0 = row0 + wm * 32 + i * 16;
#pragma unroll
        for (int j = 0; j < 4; j++) {
            int n0 = col0 + wn * 64 + j * 16;
            if (scatter) {
                int b = m0 >> 10, l = m0 & 1023;
                int h = n0 >> 6,  d = n0 & 63;
                float* dst = C + ((size_t)((b * 32 + head_off + h) * 1024 + l)) * 64 + d;
                wmma::store_matrix_sync(dst, acc[i][j], 64, wmma::mem_row_major);
            } else {
                wmma::store_matrix_sync(C + (size_t)m0 * N + n0, acc[i][j], N,
                                        wmma::mem_row_major);
            }
        }
    }
}

// ---------------------------------------------------------------------------
// RoPE + cache gather (unchanged)
// ---------------------------------------------------------------------------
__global__ void __launch_bounds__(256) rope_gather_kernel(
    const float* __restrict__ prev_k, const float* __restrict__ prev_v,
    const float* __restrict__ cosp,   const float* __restrict__ sinp)
{
    unsigned t = blockIdx.x * 256u + threadIdx.x;
    int d = t & 31;
    int l = (t >> 5) & 1023;
    int h = (t >> 15) & 31;
    int b = t >> 20;

    float c = cosp[l * 64 + d];
    float s = sinp[l * 64 + d];

    size_t base = ((size_t)(b * 32 + h) * 1024 + l) * 64;

    {
        float* q = g_Q + base;
        float x1 = q[d], x2 = q[d + 32];
        q[d]      = x1 * c - x2 * s;
        q[d + 32] = x2 * c + x1 * s;
    }
    {
        float* k = g_K + base;
        float y1, y2;
        if (h < NPREV) {
            const float* pk = prev_k + ((size_t)(b * NPREV + h) * 1024 + l) * 64;
            y1 = pk[d]; y2 = pk[d + 32];
        } else {
            y1 = k[d]; y2 = k[d + 32];
        }
        k[d]      = y1 * c - y2 * s;
        k[d + 32] = y2 * c + y1 * s;
    }
    if (h < NPREV) {
        const float* pv = prev_v + ((size_t)(b * NPREV + h) * 1024 + l) * 64;
        float* v = g_V + base;
        v[d]      = pv[d];
        v[d + 32] = pv[d + 32];
    }
}

// ---------------------------------------------------------------------------
// Flash attention (fp32, causal) — unchanged from R7 passing version
// ---------------------------------------------------------------------------
#define FA_LD 68
#define FA_SMEM (3 * 64 * FA_LD * 4)

__global__ void __launch_bounds__(256) flash_kernel(
    const float* __restrict__ Q, const float* __restrict__ K,
    const float* __restrict__ V, float* __restrict__ AO)
{
    extern __shared__ float sm[];
    float* Qs = sm;
    float* Ks = sm + 64 * FA_LD;
    float* Vs = sm + 2 * 64 * FA_LD;

    const int t  = threadIdx.x;
    const int tx = t & 15;
    const int ty = t >> 4;
    const int qt = blockIdx.x;
    const int h  = blockIdx.y;
    const int b  = blockIdx.z;
    const int q0 = qt * 64;

    const size_t bh_off = (size_t)(b * 32 + h) * 1024 * 64;
    const float* Qp = Q + bh_off;
    const float* Kp = K + bh_off;
    const float* Vp = V + bh_off;

#pragma unroll
    for (int q = 0; q < 4; q++) {
        int f  = q * 256 + t;
        int r  = f >> 4;
        int c4 = f & 15;
        float4 v = *(const float4*)(Qp + (size_t)(q0 + r) * 64 + c4 * 4);
        float* dst = Qs + r * FA_LD + c4 * 4;
        dst[0] = v.x; dst[1] = v.y; dst[2] = v.z; dst[3] = v.w;
    }

    float m_i[4], l_i[4], o_[4][4];
#pragma unroll
    for (int i = 0; i < 4; i++) {
        m_i[i] = -1e30f; l_i[i] = 0.0f;
#pragma unroll
        for (int j = 0; j < 4; j++) o_[i][j] = 0.0f;
    }

    for (int j = 0; j <= qt; j++) {
        __syncthreads();
#pragma unroll
        for (int q = 0; q < 4; q++) {
            int f  = q * 256 + t;
            int r  = f >> 4;
            int c4 = f & 15;
            size_t goff = (size_t)(j * 64 + r) * 64 + c4 * 4;
            float4 kv = *(const float4*)(Kp + goff);
            float* dk = Ks + r * FA_LD + c4 * 4;
            dk[0] = kv.x; dk[1] = kv.y; dk[2] = kv.z; dk[3] = kv.w;
            float4 vv = *(const float4*)(Vp + goff);
            float* dv = Vs + r * FA_LD + c4 * 4;
            dv[0] = vv.x; dv[1] = vv.y; dv[2] = vv.z; dv[3] = vv.w;
        }
        __syncthreads();

        float s_[4][4];
#pragma unroll
        for (int i = 0; i < 4; i++)
#pragma unroll
            for (int jj = 0; jj < 4; jj++) s_[i][jj] = 0.0f;

#pragma unroll
        for (int d4 = 0; d4 < 16; d4++) {
            float4 a[4], kk[4];
#pragma unroll
            for (int i = 0; i < 4; i++)
                a[i] = *(const float4*)(Qs + (ty * 4 + i) * FA_LD + d4 * 4);
#pragma unroll
            for (int jj = 0; jj < 4; jj++)
                kk[jj] = *(const float4*)(Ks + (jj * 16 + tx) * FA_LD + d4 * 4);
#pragma unroll
            for (int i = 0; i < 4; i++)
#pragma unroll
                for (int jj = 0; jj < 4; jj++) {
                    s_[i][jj] = fmaf(a[i].x, kk[jj].x, s_[i][jj]);
                    s_[i][jj] = fmaf(a[i].y, kk[jj].y, s_[i][jj]);
                    s_[i][jj] = fmaf(a[i].z, kk[jj].z, s_[i][jj]);
                    s_[i][jj] = fmaf(a[i].w, kk[jj].w, s_[i][jj]);
                }
        }

        const float scale = 0.125f;
#pragma unroll
        for (int i = 0; i < 4; i++)
#pragma unroll
            for (int jj = 0; jj < 4; jj++) s_[i][jj] *= scale;

        if (j == qt) {
#pragma unroll
            for (int i = 0; i < 4; i++)
#pragma unroll
                for (int jj = 0; jj < 4; jj++)
                    if ((jj * 16 + tx) > (ty * 4 + i)) s_[i][jj] = -1e30f;
        }

#pragma unroll
        for (int i = 0; i < 4; i++) {
            float mx = fmaxf(fmaxf(s_[i][0], s_[i][1]), fmaxf(s_[i][2], s_[i][3]));
#pragma unroll
            for (int off = 1; off < 16; off <<= 1)
                mx = fmaxf(mx, __shfl_xor_sync(0xffffffffu, mx, off));
            float mnew = fmaxf(m_i[i], mx);
            float corr = __expf(m_i[i] - mnew);
            float rs = 0.0f;
#pragma unroll
            for (int jj = 0; jj < 4; jj++) {
                s_[i][jj] = __expf(s_[i][jj] - mnew);
                rs += s_[i][jj];
            }
#pragma unroll
            for (int off = 1; off < 16; off <<= 1)
                rs += __shfl_xor_sync(0xffffffffu, rs, off);
            l_i[i] = l_i[i] * corr + rs;
            m_i[i] = mnew;
#pragma unroll
            for (int jj = 0; jj < 4; jj++) o_[i][jj] *= corr;
        }

        __syncthreads();
#pragma unroll
        for (int i = 0; i < 4; i++)
#pragma unroll
            for (int jj = 0; jj < 4; jj++)
                Ks[(ty * 4 + i) * FA_LD + jj * 16 + tx] = s_[i][jj];
        __syncthreads();

#pragma unroll
        for (int c4 = 0; c4 < 16; c4++) {
            float4 p4[4];
#pragma unroll
            for (int i = 0; i < 4; i++)
                p4[i] = *(const float4*)(Ks + (ty * 4 + i) * FA_LD + c4 * 4);
#pragma unroll
            for (int cc = 0; cc < 4; cc++) {
                float vv[4];
#pragma unroll
                for (int jj = 0; jj < 4; jj++)
                    vv[jj] = Vs[(c4 * 4 + cc) * FA_LD + jj * 16 + tx];
#pragma unroll
                for (int i = 0; i < 4; i++) {
                    float pval = (cc == 0) ? p4[i].x : (cc == 1) ? p4[i].y
                               : (cc == 2) ? p4[i].z : p4[i].w;
#pragma unroll
                    for (int jj = 0; jj < 4; jj++)
                        o_[i][jj] = fmaf(pval, vv[jj], o_[i][jj]);
                }
            }
        }
    }

#pragma unroll
    for (int i = 0; i < 4; i++) {
        float rl = 1.0f / l_i[i];
        size_t row = (size_t)b * 1024 + (q0 + ty * 4 + i);
#pragma unroll
        for (int jj = 0; jj < 4; jj++)
            AO[row * 2048 + h * 64 + jj * 16 + tx] = o_[i][jj] * rl;
    }
}

// ---------------------------------------------------------------------------
// Launch
// ---------------------------------------------------------------------------
extern "C" void kernel_launch(void* const* d_in, const int* in_sizes, int n_in,
                              void* d_out, int out_size)
{
    const float* hs   = (const float*)d_in[0];
    const float* pk   = (const float*)d_in[1];
    const float* pv   = (const float*)d_in[2];
    const float* Wq   = (const float*)d_in[3];
    const float* Wk   = (const float*)d_in[4];
    const float* Wv   = (const float*)d_in[5];
    const float* Wo   = (const float*)d_in[6];
    const float* cosp = (const float*)d_in[7];
    const float* sinp = (const float*)d_in[8];
    float* out = (float*)d_out;

    float *Qb, *Kb, *Vb, *AO;
    cudaGetSymbolAddress((void**)&Qb, g_Q);
    cudaGetSymbolAddress((void**)&Kb, g_K);
    cudaGetSymbolAddress((void**)&Vb, g_V);
    cudaGetSymbolAddress((void**)&AO, g_AO);

    cudaFuncSetAttribute(flash_kernel,
                         cudaFuncAttributeMaxDynamicSharedMemorySize, FA_SMEM);

    // QKV projections on tensor pipe (tf32)
    gemm_tf32<<<dim3(16, 16), 256>>>(hs, Wq, Qb, 2048, 2048, 2048, 1, 0);
    gemm_tf32<<<dim3(2, 16),  256>>>(hs, Wk, Kb, 2048, 256,  2048, 1, NPREV);
    gemm_tf32<<<dim3(2, 16),  256>>>(hs, Wv, Vb, 2048, 256,  2048, 1, NPREV);

    // Cache gather + RoPE
    rope_gather_kernel<<<8192, 256>>>(pk, pv, cosp, sinp);

    // Causal flash attention -> g_AO [B, L, 2048]
    flash_kernel<<<dim3(16, 32, 2), 256, FA_SMEM>>>(Qb, Kb, Vb, AO);

    // Output projection (tf32)
    gemm_tf32<<<dim3(16, 16), 256>>>(AO, Wo, out, 2048, 2048, 2048, 0, 0);
}

// round 11
// speedup vs baseline: 1.0391x; 1.0331x over previous
#include <cuda_runtime.h>
#include <cuda_bf16.h>
#include <mma.h>
#include <cstdint>
#include <cstddef>

using namespace nvcuda;

// Problem constants
#define BB 2
#define LL 1024
#define HH 2048
#define HD 64
#define NQ 32
#define NK 4
#define NPREV 28

// Scratch (device globals)
__device__ float g_Q[(size_t)BB * NQ * LL * HD];
__device__ float g_K[(size_t)BB * NQ * LL * HD];
__device__ float g_V[(size_t)BB * NQ * LL * HD];
__device__ float g_AO[(size_t)BB * LL * (NQ * HD)];

// ---------------------------------------------------------------------------
// TF32 tensor-core GEMM (unchanged from R10 passing version)
// ---------------------------------------------------------------------------
#define GLD 36

__global__ void __launch_bounds__(256) gemm_tf32(
    const float* __restrict__ A, const float* __restrict__ W,
    float* __restrict__ C, int M, int N, int K, int scatter, int head_off)
{
    __shared__ float As[128][GLD];
    __shared__ float Bs[128][GLD];

    const int t    = threadIdx.x;
    const int warp = t >> 5;
    const int wm   = warp & 3;
    const int wn   = warp >> 2;
    const int row0 = blockIdx.y * 128;
    const int col0 = blockIdx.x * 128;

    wmma::fragment<wmma::accumulator, 16, 16, 8, float> acc[2][4];
#pragma unroll
    for (int i = 0; i < 2; i++)
#pragma unroll
        for (int j = 0; j < 4; j++) wmma::fill_fragment(acc[i][j], 0.0f);

    for (int bk = 0; bk < K; bk += 32) {
#pragma unroll
        for (int q = 0; q < 4; q++) {
            int f  = q * 256 + t;
            int r  = f >> 3;
            int c4 = f & 7;
            float4 va = *(const float4*)(A + (size_t)(row0 + r) * K + bk + c4 * 4);
            float* da = &As[r][c4 * 4];
            da[0] = wmma::__float_to_tf32(va.x);
            da[1] = wmma::__float_to_tf32(va.y);
            da[2] = wmma::__float_to_tf32(va.z);
            da[3] = wmma::__float_to_tf32(va.w);
            float4 vb = *(const float4*)(W + (size_t)(col0 + r) * K + bk + c4 * 4);
            float* db = &Bs[r][c4 * 4];
            db[0] = wmma::__float_to_tf32(vb.x);
            db[1] = wmma::__float_to_tf32(vb.y);
            db[2] = wmma::__float_to_tf32(vb.z);
            db[3] = wmma::__float_to_tf32(vb.w);
        }
        __syncthreads();

#pragma unroll
        for (int ks = 0; ks < 4; ks++) {
            wmma::fragment<wmma::matrix_a, 16, 16, 8, wmma::precision::tf32,
                           wmma::row_major> af[2];
#pragma unroll
            for (int i = 0; i < 2; i++)
                wmma::load_matrix_sync(af[i], &As[wm * 32 + i * 16][ks * 8], GLD);
#pragma unroll
            for (int j = 0; j < 4; j++) {
                wmma::fragment<wmma::matrix_b, 16, 16, 8, wmma::precision::tf32,
                               wmma::col_major> bf;
                wmma::load_matrix_sync(bf, &Bs[wn * 64 + j * 16][ks * 8], GLD);
#pragma unroll
                for (int i = 0; i < 2; i++)
                    wmma::mma_sync(acc[i][j], af[i], bf, acc[i][j]);
            }
        }
        __syncthreads();
    }

#pragma unroll
    for (int i = 0; i < 2; i++) {
        int m0 = row0 + wm * 32 + i * 16;
#pragma unroll
        for (int j = 0; j < 4; j++) {
            int n0 = col0 + wn * 64 + j * 16;
            if (scatter) {
                int b = m0 >> 10, l = m0 & 1023;
                int h = n0 >> 6,  d = n0 & 63;
                float* dst = C + ((size_t)((b * 32 + head_off + h) * 1024 + l)) * 64 + d;
                wmma::store_matrix_sync(dst, acc[i][j], 64, wmma::mem_row_major);
            } else {
                wmma::store_matrix_sync(C + (size_t)m0 * N + n0, acc[i][j], N,
                                        wmma::mem_row_major);
            }
        }
    }
}

// ---------------------------------------------------------------------------
// RoPE + cache gather (unchanged)
// ---------------------------------------------------------------------------
__global__ void __launch_bounds__(256) rope_gather_kernel(
    const float* __restrict__ prev_k, const float* __restrict__ prev_v,
    const float* __restrict__ cosp,   const float* __restrict__ sinp)
{
    unsigned t = blockIdx.x * 256u + threadIdx.x;
    int d = t & 31;
    int l = (t >> 5) & 1023;
    int h = (t >> 15) & 31;
    int b = t >> 20;

    float c = cosp[l * 64 + d];
    float s = sinp[l * 64 + d];

    size_t base = ((size_t)(b * 32 + h) * 1024 + l) * 64;

    {
        float* q = g_Q + base;
        float x1 = q[d], x2 = q[d + 32];
        q[d]      = x1 * c - x2 * s;
        q[d + 32] = x2 * c + x1 * s;
    }
    {
        float* k = g_K + base;
        float y1, y2;
        if (h < NPREV) {
            const float* pk = prev_k + ((size_t)(b * NPREV + h) * 1024 + l) * 64;
            y1 = pk[d]; y2 = pk[d + 32];
        } else {
            y1 = k[d]; y2 = k[d + 32];
        }
        k[d]      = y1 * c - y2 * s;
        k[d + 32] = y2 * c + y1 * s;
    }
    if (h < NPREV) {
        const float* pv = prev_v + ((size_t)(b * NPREV + h) * 1024 + l) * 64;
        float* v = g_V + base;
        v[d]      = pv[d];
        v[d + 32] = pv[d + 32];
    }
}

// ---------------------------------------------------------------------------
// Flash attention on tensor cores (tf32 wmma), causal. BR=BC=64, 256 thr.
// S = QK^T via wmma (K col_major). Softmax SIMT: 4 threads/row, row state in
// registers. O kept in smem fp32; PV accumulates via load/mma/store.
// ---------------------------------------------------------------------------
#define FLD 68
#define FSM (5 * 64 * FLD * 4)

__global__ void __launch_bounds__(256) flash_wmma(
    const float* __restrict__ Q, const float* __restrict__ K,
    const float* __restrict__ V, float* __restrict__ AO)
{
    extern __shared__ float sm[];
    float* Qs = sm;                 // 64 x FLD, tf32
    float* Ks = sm + 64 * FLD;      // tf32
    float* Vs = sm + 2 * 64 * FLD;  // tf32
    float* Ss = sm + 3 * 64 * FLD;  // fp32 scores -> tf32 P
    float* Os = sm + 4 * 64 * FLD;  // fp32 O accumulator

    const int t    = threadIdx.x;
    const int warp = t >> 5;
    const int wm   = warp & 3;   // 4 warps along rows (16 each)
    const int wn   = warp >> 2;  // 2 warps along cols (32 each)
    const int qt   = blockIdx.x;
    const int h    = blockIdx.y;
    const int b    = blockIdx.z;
    const int q0   = qt * 64;

    const size_t bh_off = (size_t)(b * 32 + h) * 1024 * 64;
    const float* Qp = Q + bh_off;
    const float* Kp = K + bh_off;
    const float* Vp = V + bh_off;

    // Load Q tile (tf32 convert) and zero O
#pragma unroll
    for (int q = 0; q < 4; q++) {
        int f  = q * 256 + t;
        int r  = f >> 4;
        int c4 = f & 15;
        float4 v = *(const float4*)(Qp + (size_t)(q0 + r) * 64 + c4 * 4);
        float* dq = Qs + r * FLD + c4 * 4;
        dq[0] = wmma::__float_to_tf32(v.x);
        dq[1] = wmma::__float_to_tf32(v.y);
        dq[2] = wmma::__float_to_tf32(v.z);
        dq[3] = wmma::__float_to_tf32(v.w);
        float4 z = make_float4(0.f, 0.f, 0.f, 0.f);
        *(float4*)(Os + r * FLD + c4 * 4) = z;
    }

    // Per-thread softmax row state: thread t owns row t>>2, cols (t&3)*16..+15
    const int srow = t >> 2;
    const int scol = (t & 3) * 16;
    float m_r = -1e30f, l_r = 0.0f;

    for (int j = 0; j <= qt; j++) {
        __syncthreads();   // Vs/Ss/Os consumers from prev iter done
        // Load K, V tiles (tf32)
#pragma unroll
        for (int q = 0; q < 4; q++) {
            int f  = q * 256 + t;
            int r  = f >> 4;
            int c4 = f & 15;
            size_t goff = (size_t)(j * 64 + r) * 64 + c4 * 4;
            float4 kv = *(const float4*)(Kp + goff);
            float* dk = Ks + r * FLD + c4 * 4;
            dk[0] = wmma::__float_to_tf32(kv.x);
            dk[1] = wmma::__float_to_tf32(kv.y);
            dk[2] = wmma::__float_to_tf32(kv.z);
            dk[3] = wmma::__float_to_tf32(kv.w);
            float4 vv = *(const float4*)(Vp + goff);
            float* dv = Vs + r * FLD + c4 * 4;
            dv[0] = wmma::__float_to_tf32(vv.x);
            dv[1] = wmma::__float_to_tf32(vv.y);
            dv[2] = wmma::__float_to_tf32(vv.z);
            dv[3] = wmma::__float_to_tf32(vv.w);
        }
        __syncthreads();

        // S = Q @ K^T : warp computes rows wm*16..+15, cols wn*32..+31
        {
            wmma::fragment<wmma::accumulator, 16, 16, 8, float> sacc[2];
#pragma unroll
            for (int n = 0; n < 2; n++) wmma::fill_fragment(sacc[n], 0.0f);
#pragma unroll
            for (int ks = 0; ks < 8; ks++) {
                wmma::fragment<wmma::matrix_a, 16, 16, 8, wmma::precision::tf32,
                               wmma::row_major> af;
                wmma::load_matrix_sync(af, Qs + (wm * 16) * FLD + ks * 8, FLD);
#pragma unroll
                for (int n = 0; n < 2; n++) {
                    wmma::fragment<wmma::matrix_b, 16, 16, 8, wmma::precision::tf32,
                                   wmma::col_major> bf;
                    wmma::load_matrix_sync(bf, Ks + (wn * 32 + n * 16) * FLD + ks * 8, FLD);
                    wmma::mma_sync(sacc[n], af, bf, sacc[n]);
                }
            }
#pragma unroll
            for (int n = 0; n < 2; n++)
                wmma::store_matrix_sync(Ss + (wm * 16) * FLD + wn * 32 + n * 16,
                                        sacc[n], FLD, wmma::mem_row_major);
        }
        __syncthreads();

        // Softmax on 16 scores of (srow, scol..+15)
        {
            float sv[16];
#pragma unroll
            for (int i4 = 0; i4 < 4; i4++) {
                float4 v = *(const float4*)(Ss + srow * FLD + scol + i4 * 4);
                sv[i4 * 4 + 0] = v.x * 0.125f;
                sv[i4 * 4 + 1] = v.y * 0.125f;
                sv[i4 * 4 + 2] = v.z * 0.125f;
                sv[i4 * 4 + 3] = v.w * 0.125f;
            }
            if (j == qt) {
#pragma unroll
                for (int i = 0; i < 16; i++)
                    if (scol + i > srow) sv[i] = -1e30f;
            }
            float mx = sv[0];
#pragma unroll
            for (int i = 1; i < 16; i++) mx = fmaxf(mx, sv[i]);
            mx = fmaxf(mx, __shfl_xor_sync(0xffffffffu, mx, 1));
            mx = fmaxf(mx, __shfl_xor_sync(0xffffffffu, mx, 2));
            float mnew = fmaxf(m_r, mx);
            float corr = __expf(m_r - mnew);
            float rs = 0.0f;
#pragma unroll
            for (int i = 0; i < 16; i++) {
                sv[i] = __expf(sv[i] - mnew);
                rs += sv[i];
            }
            rs += __shfl_xor_sync(0xffffffffu, rs, 1);
            rs += __shfl_xor_sync(0xffffffffu, rs, 2);
            l_r = l_r * corr + rs;
            m_r = mnew;
            // write P (tf32) back to Ss; rescale O row chunk
#pragma unroll
            for (int i4 = 0; i4 < 4; i4++) {
                float4 p;
                p.x = wmma::__float_to_tf32(sv[i4 * 4 + 0]);
                p.y = wmma::__float_to_tf32(sv[i4 * 4 + 1]);
                p.z = wmma::__float_to_tf32(sv[i4 * 4 + 2]);
                p.w = wmma::__float_to_tf32(sv[i4 * 4 + 3]);
                *(float4*)(Ss + srow * FLD + scol + i4 * 4) = p;
                float4 o = *(const float4*)(Os + srow * FLD + scol + i4 * 4);
                o.x *= corr; o.y *= corr; o.z *= corr; o.w *= corr;
                *(float4*)(Os + srow * FLD + scol + i4 * 4) = o;
            }
        }
        __syncthreads();

        // O += P @ V : warp does rows wm*16..+15, d-cols wn*32..+31
        {
            wmma::fragment<wmma::accumulator, 16, 16, 8, float> oacc[2];
#pragma unroll
            for (int n = 0; n < 2; n++)
                wmma::load_matrix_sync(oacc[n],
                    Os + (wm * 16) * FLD + wn * 32 + n * 16, FLD, wmma::mem_row_major);
#pragma unroll
            for (int ks = 0; ks < 8; ks++) {
                wmma::fragment<wmma::matrix_a, 16, 16, 8, wmma::precision::tf32,
                               wmma::row_major> af;
                wmma::load_matrix_sync(af, Ss + (wm * 16) * FLD + ks * 8, FLD);
#pragma unroll
                for (int n = 0; n < 2; n++) {
                    wmma::fragment<wmma::matrix_b, 16, 16, 8, wmma::precision::tf32,
                                   wmma::row_major> bf;
                    wmma::load_matrix_sync(bf, Vs + (ks * 8) * FLD + wn * 32 + n * 16, FLD);
                    wmma::mma_sync(oacc[n], af, bf, oacc[n]);
                }
            }
#pragma unroll
            for (int n = 0; n < 2; n++)
                wmma::store_matrix_sync(Os + (wm * 16) * FLD + wn * 32 + n * 16,
                                        oacc[n], FLD, wmma::mem_row_major);
        }
    }
    __syncthreads();

    // Epilogue: normalize and write AO[b, q0+srow, h*64 + scol..+15]
    {
        float rl = 1.0f / l_r;
        size_t row = (size_t)b * 1024 + (q0 + srow);
        float* dst = AO + row * 2048 + h * 64 + scol;
#pragma unroll
        for (int i4 = 0; i4 < 4; i4++) {
            float4 o = *(const float4*)(Os + srow * FLD + scol + i4 * 4);
            o.x *= rl; o.y *= rl; o.z *= rl; o.w *= rl;
            *(float4*)(dst + i4 * 4) = o;
        }
    }
}

// ---------------------------------------------------------------------------
// Launch
// ---------------------------------------------------------------------------
extern "C" void kernel_launch(void* const* d_in, const int* in_sizes, int n_in,
                              void* d_out, int out_size)
{
    const float* hs   = (const float*)d_in[0];
    const float* pk   = (const float*)d_in[1];
    const float* pv   = (const float*)d_in[2];
    const float* Wq   = (const float*)d_in[3];
    const float* Wk   = (const float*)d_in[4];
    const float* Wv   = (const float*)d_in[5];
    const float* Wo   = (const float*)d_in[6];
    const float* cosp = (const float*)d_in[7];
    const float* sinp = (const float*)d_in[8];
    float* out = (float*)d_out;

    float *Qb, *Kb, *Vb, *AO;
    cudaGetSymbolAddress((void**)&Qb, g_Q);
    cudaGetSymbolAddress((void**)&Kb, g_K);
    cudaGetSymbolAddress((void**)&Vb, g_V);
    cudaGetSymbolAddress((void**)&AO, g_AO);

    cudaFuncSetAttribute(flash_wmma,
                         cudaFuncAttributeMaxDynamicSharedMemorySize, FSM);

    // QKV projections (tf32 tensor cores)
    gemm_tf32<<<dim3(16, 16), 256>>>(hs, Wq, Qb, 2048, 2048, 2048, 1, 0);
    gemm_tf32<<<dim3(2, 16),  256>>>(hs, Wk, Kb, 2048, 256,  2048, 1, NPREV);
    gemm_tf32<<<dim3(2, 16),  256>>>(hs, Wv, Vb, 2048, 256,  2048, 1, NPREV);

    // Cache gather + RoPE
    rope_gather_kernel<<<8192, 256>>>(pk, pv, cosp, sinp);

    // Causal flash attention (tensor cores) -> g_AO [B, L, 2048]
    flash_wmma<<<dim3(16, 32, 2), 256, FSM>>>(Qb, Kb, Vb, AO);

    // Output projection (tf32)
    gemm_tf32<<<dim3(16, 16), 256>>>(AO, Wo, out, 2048, 2048, 2048, 0, 0);
}

// round 12
// speedup vs baseline: 1.6066x; 1.5461x over previous
#include <cuda_runtime.h>
#include <cuda_bf16.h>
#include <mma.h>
#include <cstdint>
#include <cstddef>

using namespace nvcuda;

// Problem constants
#define BB 2
#define LL 1024
#define HH 2048
#define HD 64
#define NQ 32
#define NK 4
#define NPREV 28

// Scratch (device globals)
__device__ float g_Q[(size_t)BB * NQ * LL * HD];
__device__ float g_K[(size_t)BB * NQ * LL * HD];
__device__ float g_V[(size_t)BB * NQ * LL * HD];
__device__ float g_AO[(size_t)BB * LL * (NQ * HD)];

// ---------------------------------------------------------------------------
// Double-buffered TF32 GEMM: C = A @ W^T.  A:[M,K] rm, W:[N,K] rm.
// BK=16, register prefetch -> tf32 convert -> STS, 1 sync per K-step.
// MODE 0: C1[m*N+n] plain.
// MODE 1: Q scatter  -> C1[((b*32+h)*1024+l)*64+d]
// MODE 2: fused KV   -> heads 0-3 from W1 -> C1 (K, head NPREV+h),
//                       heads 4-7 from W2 -> C2 (V, head NPREV+h-4)
// ---------------------------------------------------------------------------
#define LDS 20   // smem row stride (floats): 80B, 16B aligned, conflict-benign

template<int BM, int BN, int WARPS_M, int WARPS_N, int MODE>
__global__ void __launch_bounds__(256, 2) gemm_pipe(
    const float* __restrict__ A, const float* __restrict__ W1,
    const float* __restrict__ W2, float* __restrict__ C1,
    float* __restrict__ C2, int M, int N, int K)
{
    constexpr int MI  = BM / (16 * WARPS_M);
    constexpr int NJ  = BN / (16 * WARPS_N);
    constexpr int APT = BM * 4 / 256;   // float4 per thread, A stage
    constexpr int BPT = BN * 4 / 256;

    __shared__ __align__(16) float As[2][BM][LDS];
    __shared__ __align__(16) float Bs[2][BN][LDS];

    const int t    = threadIdx.x;
    const int warp = t >> 5;
    const int wm   = warp % WARPS_M;
    const int wn   = warp / WARPS_M;
    const int row0 = blockIdx.y * BM;
    const int col0 = blockIdx.x * BN;

    // Precompute per-thread source row pointers (loop-invariant)
    const float* aptr[APT];
    int ar[APT], ac[APT];
#pragma unroll
    for (int q = 0; q < APT; q++) {
        int f = q * 256 + t;
        ar[q] = f >> 2; ac[q] = (f & 3) * 4;
        aptr[q] = A + (size_t)(row0 + ar[q]) * K + ac[q];
    }
    const float* bptr[BPT];
    int br[BPT], bc[BPT];
#pragma unroll
    for (int q = 0; q < BPT; q++) {
        int f = q * 256 + t;
        br[q] = f >> 2; bc[q] = (f & 3) * 4;
        int rw = col0 + br[q];
        const float* src;
        if (MODE == 2) src = (rw < 256) ? (W1 + (size_t)rw * K)
                                        : (W2 + (size_t)(rw - 256) * K);
        else           src = W1 + (size_t)rw * K;
        bptr[q] = src + bc[q];
    }

    wmma::fragment<wmma::accumulator, 16, 16, 8, float> acc[MI][NJ];
#pragma unroll
    for (int i = 0; i < MI; i++)
#pragma unroll
        for (int j = 0; j < NJ; j++) wmma::fill_fragment(acc[i][j], 0.0f);

    float4 ra[APT], rb[BPT];

    auto ldg = [&](int bk) {
#pragma unroll
        for (int q = 0; q < APT; q++) ra[q] = *(const float4*)(aptr[q] + bk);
#pragma unroll
        for (int q = 0; q < BPT; q++) rb[q] = *(const float4*)(bptr[q] + bk);
    };
    auto sts = [&](int buf) {
#pragma unroll
        for (int q = 0; q < APT; q++) {
            float* d = &As[buf][ar[q]][ac[q]];
            d[0] = wmma::__float_to_tf32(ra[q].x);
            d[1] = wmma::__float_to_tf32(ra[q].y);
            d[2] = wmma::__float_to_tf32(ra[q].z);
            d[3] = wmma::__float_to_tf32(ra[q].w);
        }
#pragma unroll
        for (int q = 0; q < BPT; q++) {
            float* d = &Bs[buf][br[q]][bc[q]];
            d[0] = wmma::__float_to_tf32(rb[q].x);
            d[1] = wmma::__float_to_tf32(rb[q].y);
            d[2] = wmma::__float_to_tf32(rb[q].z);
            d[3] = wmma::__float_to_tf32(rb[q].w);
        }
    };
    auto compute = [&](int buf) {
#pragma unroll
        for (int ks = 0; ks < 2; ks++) {
            wmma::fragment<wmma::matrix_a, 16, 16, 8, wmma::precision::tf32,
                           wmma::row_major> af[MI];
#pragma unroll
            for (int i = 0; i < MI; i++)
                wmma::load_matrix_sync(af[i],
                    &As[buf][(wm * MI + i) * 16][ks * 8], LDS);
#pragma unroll
            for (int j = 0; j < NJ; j++) {
                wmma::fragment<wmma::matrix_b, 16, 16, 8, wmma::precision::tf32,
                               wmma::col_major> bf;
                wmma::load_matrix_sync(bf,
                    &Bs[buf][(wn * NJ + j) * 16][ks * 8], LDS);
#pragma unroll
                for (int i = 0; i < MI; i++)
                    wmma::mma_sync(acc[i][j], af[i], bf, acc[i][j]);
            }
        }
    };

    // Pipeline
    const int nit = K / 16;
    ldg(0);
    sts(0);
    __syncthreads();
    for (int i = 0; i < nit; i++) {
        int buf = i & 1;
        if (i + 1 < nit) ldg((i + 1) * 16);
        compute(buf);
        if (i + 1 < nit) {
            sts(buf ^ 1);
            __syncthreads();
        }
    }

    // Epilogue
#pragma unroll
    for (int i = 0; i < MI; i++) {
        int m0 = row0 + (wm * MI + i) * 16;
#pragma unroll
        for (int j = 0; j < NJ; j++) {
            int n0 = col0 + (wn * NJ + j) * 16;
            if (MODE == 0) {
                wmma::store_matrix_sync(C1 + (size_t)m0 * N + n0, acc[i][j], N,
                                        wmma::mem_row_major);
            } else if (MODE == 1) {
                int b = m0 >> 10, l = m0 & 1023;
                int h = n0 >> 6,  d = n0 & 63;
                float* dst = C1 + ((size_t)((b * 32 + h) * 1024 + l)) * 64 + d;
                wmma::store_matrix_sync(dst, acc[i][j], 64, wmma::mem_row_major);
            } else {
                int b = m0 >> 10, l = m0 & 1023;
                int h = n0 >> 6,  d = n0 & 63;
                float* dst;
                if (h < 4)
                    dst = C1 + ((size_t)((b * 32 + NPREV + h) * 1024 + l)) * 64 + d;
                else
                    dst = C2 + ((size_t)((b * 32 + NPREV + h - 4) * 1024 + l)) * 64 + d;
                wmma::store_matrix_sync(dst, acc[i][j], 64, wmma::mem_row_major);
            }
        }
    }
}

// ---------------------------------------------------------------------------
// RoPE + cache gather (unchanged)
// ---------------------------------------------------------------------------
__global__ void __launch_bounds__(256) rope_gather_kernel(
    const float* __restrict__ prev_k, const float* __restrict__ prev_v,
    const float* __restrict__ cosp,   const float* __restrict__ sinp)
{
    unsigned t = blockIdx.x * 256u + threadIdx.x;
    int d = t & 31;
    int l = (t >> 5) & 1023;
    int h = (t >> 15) & 31;
    int b = t >> 20;

    float c = cosp[l * 64 + d];
    float s = sinp[l * 64 + d];

    size_t base = ((size_t)(b * 32 + h) * 1024 + l) * 64;

    {
        float* q = g_Q + base;
        float x1 = q[d], x2 = q[d + 32];
        q[d]      = x1 * c - x2 * s;
        q[d + 32] = x2 * c + x1 * s;
    }
    {
        float* k = g_K + base;
        float y1, y2;
        if (h < NPREV) {
            const float* pk = prev_k + ((size_t)(b * NPREV + h) * 1024 + l) * 64;
            y1 = pk[d]; y2 = pk[d + 32];
        } else {
            y1 = k[d]; y2 = k[d + 32];
        }
        k[d]      = y1 * c - y2 * s;
        k[d + 32] = y2 * c + y1 * s;
    }
    if (h < NPREV) {
        const float* pv = prev_v + ((size_t)(b * NPREV + h) * 1024 + l) * 64;
        float* v = g_V + base;
        v[d]      = pv[d];
        v[d + 32] = pv[d + 32];
    }
}

// ---------------------------------------------------------------------------
// Flash attention on tensor cores (tf32 wmma) — unchanged from R11 passing
// ---------------------------------------------------------------------------
#define FLD 68
#define FSM (5 * 64 * FLD * 4)

__global__ void __launch_bounds__(256) flash_wmma(
    const float* __restrict__ Q, const float* __restrict__ K,
    const float* __restrict__ V, float* __restrict__ AO)
{
    extern __shared__ float sm[];
    float* Qs = sm;
    float* Ks = sm + 64 * FLD;
    float* Vs = sm + 2 * 64 * FLD;
    float* Ss = sm + 3 * 64 * FLD;
    float* Os = sm + 4 * 64 * FLD;

    const int t    = threadIdx.x;
    const int warp = t >> 5;
    const int wm   = warp & 3;
    const int wn   = warp >> 2;
    const int qt   = blockIdx.x;
    const int h    = blockIdx.y;
    const int b    = blockIdx.z;
    const int q0   = qt * 64;

    const size_t bh_off = (size_t)(b * 32 + h) * 1024 * 64;
    const float* Qp = Q + bh_off;
    const float* Kp = K + bh_off;
    const float* Vp = V + bh_off;

#pragma unroll
    for (int q = 0; q < 4; q++) {
        int f  = q * 256 + t;
        int r  = f >> 4;
        int c4 = f & 15;
        float4 v = *(const float4*)(Qp + (size_t)(q0 + r) * 64 + c4 * 4);
        float* dq = Qs + r * FLD + c4 * 4;
        dq[0] = wmma::__float_to_tf32(v.x);
        dq[1] = wmma::__float_to_tf32(v.y);
        dq[2] = wmma::__float_to_tf32(v.z);
        dq[3] = wmma::__float_to_tf32(v.w);
        float4 z = make_float4(0.f, 0.f, 0.f, 0.f);
        *(float4*)(Os + r * FLD + c4 * 4) = z;
    }

    const int srow = t >> 2;
    const int scol = (t & 3) * 16;
    float m_r = -1e30f, l_r = 0.0f;

    for (int j = 0; j <= qt; j++) {
        __syncthreads();
#pragma unroll
        for (int q = 0; q < 4; q++) {
            int f  = q * 256 + t;
            int r  = f >> 4;
            int c4 = f & 15;
            size_t goff = (size_t)(j * 64 + r) * 64 + c4 * 4;
            float4 kv = *(const float4*)(Kp + goff);
            float* dk = Ks + r * FLD + c4 * 4;
            dk[0] = wmma::__float_to_tf32(kv.x);
            dk[1] = wmma::__float_to_tf32(kv.y);
            dk[2] = wmma::__float_to_tf32(kv.z);
            dk[3] = wmma::__float_to_tf32(kv.w);
            float4 vv = *(const float4*)(Vp + goff);
            float* dv = Vs + r * FLD + c4 * 4;
            dv[0] = wmma::__float_to_tf32(vv.x);
            dv[1] = wmma::__float_to_tf32(vv.y);
            dv[2] = wmma::__float_to_tf32(vv.z);
            dv[3] = wmma::__float_to_tf32(vv.w);
        }
        __syncthreads();

        {
            wmma::fragment<wmma::accumulator, 16, 16, 8, float> sacc[2];
#pragma unroll
            for (int n = 0; n < 2; n++) wmma::fill_fragment(sacc[n], 0.0f);
#pragma unroll
            for (int ks = 0; ks < 8; ks++) {
                wmma::fragment<wmma::matrix_a, 16, 16, 8, wmma::precision::tf32,
                               wmma::row_major> af;
                wmma::load_matrix_sync(af, Qs + (wm * 16) * FLD + ks * 8, FLD);
#pragma unroll
                for (int n = 0; n < 2; n++) {
                    wmma::fragment<wmma::matrix_b, 16, 16, 8, wmma::precision::tf32,
                                   wmma::col_major> bf;
                    wmma::load_matrix_sync(bf, Ks + (wn * 32 + n * 16) * FLD + ks * 8, FLD);
                    wmma::mma_sync(sacc[n], af, bf, sacc[n]);
                }
            }
#pragma unroll
            for (int n = 0; n < 2; n++)
                wmma::store_matrix_sync(Ss + (wm * 16) * FLD + wn * 32 + n * 16,
                                        sacc[n], FLD, wmma::mem_row_major);
        }
        __syncthreads();

        {
            float sv[16];
#pragma unroll
            for (int i4 = 0; i4 < 4; i4++) {
                float4 v = *(const float4*)(Ss + srow * FLD + scol + i4 * 4);
                sv[i4 * 4 + 0] = v.x * 0.125f;
                sv[i4 * 4 + 1] = v.y * 0.125f;
                sv[i4 * 4 + 2] = v.z * 0.125f;
                sv[i4 * 4 + 3] = v.w * 0.125f;
            }
            if (j == qt) {
#pragma unroll
                for (int i = 0; i < 16; i++)
                    if (scol + i > srow) sv[i] = -1e30f;
            }
            float mx = sv[0];
#pragma unroll
            for (int i = 1; i < 16; i++) mx = fmaxf(mx, sv[i]);
            mx = fmaxf(mx, __shfl_xor_sync(0xffffffffu, mx, 1));
            mx = fmaxf(mx, __shfl_xor_sync(0xffffffffu, mx, 2));
            float mnew = fmaxf(m_r, mx);
            float corr = __expf(m_r - mnew);
            float rs = 0.0f;
#pragma unroll
            for (int i = 0; i < 16; i++) {
                sv[i] = __expf(sv[i] - mnew);
                rs += sv[i];
            }
            rs += __shfl_xor_sync(0xffffffffu, rs, 1);
            rs += __shfl_xor_sync(0xffffffffu, rs, 2);
            l_r = l_r * corr + rs;
            m_r = mnew;
#pragma unroll
            for (int i4 = 0; i4 < 4; i4++) {
                float4 p;
                p.x = wmma::__float_to_tf32(sv[i4 * 4 + 0]);
                p.y = wmma::__float_to_tf32(sv[i4 * 4 + 1]);
                p.z = wmma::__float_to_tf32(sv[i4 * 4 + 2]);
                p.w = wmma::__float_to_tf32(sv[i4 * 4 + 3]);
                *(float4*)(Ss + srow * FLD + scol + i4 * 4) = p;
                float4 o = *(const float4*)(Os + srow * FLD + scol + i4 * 4);
                o.x *= corr; o.y *= corr; o.z *= corr; o.w *= corr;
                *(float4*)(Os + srow * FLD + scol + i4 * 4) = o;
            }
        }
        __syncthreads();

        {
            wmma::fragment<wmma::accumulator, 16, 16, 8, float> oacc[2];
#pragma unroll
            for (int n = 0; n < 2; n++)
                wmma::load_matrix_sync(oacc[n],
                    Os + (wm * 16) * FLD + wn * 32 + n * 16, FLD, wmma::mem_row_major);
#pragma unroll
            for (int ks = 0; ks < 8; ks++) {
                wmma::fragment<wmma::matrix_a, 16, 16, 8, wmma::precision::tf32,
                               wmma::row_major> af;
                wmma::load_matrix_sync(af, Ss + (wm * 16) * FLD + ks * 8, FLD);
#pragma unroll
                for (int n = 0; n < 2; n++) {
                    wmma::fragment<wmma::matrix_b, 16, 16, 8, wmma::precision::tf32,
                                   wmma::row_major> bf;
                    wmma::load_matrix_sync(bf, Vs + (ks * 8) * FLD + wn * 32 + n * 16, FLD);
                    wmma::mma_sync(oacc[n], af, bf, oacc[n]);
                }
            }
#pragma unroll
            for (int n = 0; n < 2; n++)
                wmma::store_matrix_sync(Os + (wm * 16) * FLD + wn * 32 + n * 16,
                                        oacc[n], FLD, wmma::mem_row_major);
        }
    }
    __syncthreads();

    {
        float rl = 1.0f / l_r;
        size_t row = (size_t)b * 1024 + (q0 + srow);
        float* dst = AO + row * 2048 + h * 64 + scol;
#pragma unroll
        for (int i4 = 0; i4 < 4; i4++) {
            float4 o = *(const float4*)(Os + srow * FLD + scol + i4 * 4);
            o.x *= rl; o.y *= rl; o.z *= rl; o.w *= rl;
            *(float4*)(dst + i4 * 4) = o;
        }
    }
}

// ---------------------------------------------------------------------------
// Launch
// ---------------------------------------------------------------------------
extern "C" void kernel_launch(void* const* d_in, const int* in_sizes, int n_in,
                              void* d_out, int out_size)
{
    const float* hs   = (const float*)d_in[0];
    const float* pk   = (const float*)d_in[1];
    const float* pv   = (const float*)d_in[2];
    const float* Wq   = (const float*)d_in[3];
    const float* Wk   = (const float*)d_in[4];
    const float* Wv   = (const float*)d_in[5];
    const float* Wo   = (const float*)d_in[6];
    const float* cosp = (const float*)d_in[7];
    const float* sinp = (const float*)d_in[8];
    float* out = (float*)d_out;

    float *Qb, *Kb, *Vb, *AO;
    cudaGetSymbolAddress((void**)&Qb, g_Q);
    cudaGetSymbolAddress((void**)&Kb, g_K);
    cudaGetSymbolAddress((void**)&Vb, g_V);
    cudaGetSymbolAddress((void**)&AO, g_AO);

    cudaFuncSetAttribute(flash_wmma,
                         cudaFuncAttributeMaxDynamicSharedMemorySize, FSM);

    // Q projection (scatter into [B,h,L,64])
    gemm_pipe<128, 128, 4, 2, 1><<<dim3(16, 16), 256>>>(
        hs, Wq, nullptr, Qb, nullptr, 2048, 2048, 2048);
    // Fused K+V projection (128 blocks)
    gemm_pipe<64, 128, 2, 4, 2><<<dim3(4, 32), 256>>>(
        hs, Wk, Wv, Kb, Vb, 2048, 512, 2048);

    // Cache gather + RoPE
    rope_gather_kernel<<<8192, 256>>>(pk, pv, cosp, sinp);

    // Causal flash attention (tensor cores) -> g_AO [B, L, 2048]
    flash_wmma<<<dim3(16, 32, 2), 256, FSM>>>(Qb, Kb, Vb, AO);

    // Output projection
    gemm_pipe<128, 128, 4, 2, 0><<<dim3(16, 16), 256>>>(
        AO, Wo, nullptr, out, nullptr, 2048, 2048, 2048);
}